// round 10
// baseline (speedup 1.0000x reference)
#include <cuda_runtime.h>

#define MAXE   1600000
#define MAXN   100352
#define CB     4             // x slices (each fits in smem)
#define NSLOT  4736          // 148 SMs * 32 warps
#define MAXELL 6000000
#define N_IT   7
#define BLK    1024
#define DEGBINS 1024

// ---------------- scratch (no allocations allowed) ----------------
// d_cntp / d_cursc / d_sinkw / d_total zeroed by solve's epilogue for the
// next call (zero-initialized at module load for the first call).
__device__ float    d_w[MAXE];          // exp(rewards), original edge order
__device__ float2   d_ell[MAXELL];      // warp-transposed ELL: {w, bitcast(rel_dst)}
__device__ unsigned d_cntp[MAXN];       // packed per-slice counts (byte c = slice c)
__device__ int      d_cursc[CB * MAXN]; // scatter cursors per (slice, node)
__device__ float    d_sinkw[MAXN];      // sum of w over edges i->sink
__device__ float    d_xa[MAXN];
__device__ float    d_xb[MAXN];
__device__ int      d_perm[MAXN];       // nodes sorted by total degree
__device__ int      d_inv[MAXN];        // inverse permutation
__device__ int      d_elloff4[NSLOT * CB]; // ELL base offset per (slot, slice)
__device__ int      d_total;            // ELL bump allocator
__device__ unsigned d_flags[256];       // per-block barrier generation flags

// ---------------- setup kernels ----------------

// Warp-cooperative rewards: 4 edges/warp; 32 lanes read 32 consecutive
// float4s (512B coalesced); 8-lane shfl reduce. Single packed atomic counts
// the edge into its dst-slice byte.
__global__ void rewards_kernel(const float* __restrict__ feats,
                               const float* __restrict__ W,
                               const float* __restrict__ b,
                               const int* __restrict__ src,
                               const int* __restrict__ dst,
                               const unsigned char* __restrict__ mask,
                               float* __restrict__ out_rewards,
                               int E, int S) {
    const int tid = blockIdx.x * blockDim.x + threadIdx.x;
    if (tid < 256) d_flags[tid] = 0;
    const int lane = threadIdx.x & 31;
    const int gw = tid >> 5;
    const int sub = lane >> 3;
    const int ch  = lane & 7;
    const int e = gw * 4 + sub;
    if (gw * 4 >= E) return;

    float part = 0.0f;
    if (e < E) {
        float4 v = __ldg(&reinterpret_cast<const float4*>(feats)[(size_t)e * 8 + ch]);
        part = v.x * __ldg(&W[ch * 4 + 0]) + v.y * __ldg(&W[ch * 4 + 1])
             + v.z * __ldg(&W[ch * 4 + 2]) + v.w * __ldg(&W[ch * 4 + 3]);
    }
    part += __shfl_down_sync(0xffffffffu, part, 4, 8);
    part += __shfl_down_sync(0xffffffffu, part, 2, 8);
    part += __shfl_down_sync(0xffffffffu, part, 1, 8);

    if (e < E && ch == 0) {
        float z = part + __ldg(b);
        float sp = fmaxf(z, 0.0f) + log1pf(expf(-fabsf(z)));   // stable softplus
        float r = -sp;
        out_rewards[e] = r;
        float w = expf(r);
        d_w[e] = w;
        int s = src[e];
        int d = dst[e];
        if (mask[d])
            atomicAdd(&d_sinkw[s], w);   // x[sink] == 1 always: fold into constant
        else
            atomicAdd(&d_cntp[s], 1u << (8 * (d / S)));
    }
}

__device__ __forceinline__ int total_deg(unsigned p) {
    return (int)((p & 255u) + ((p >> 8) & 255u) + ((p >> 16) & 255u) + (p >> 24));
}

// single block: counting-sort permutation by total degree (smem bins)
__global__ void build_perm_kernel(int n) {
    __shared__ int bins[DEGBINS];
    __shared__ int curs[DEGBINS];
    int t = threadIdx.x;
    bins[t] = 0;
    __syncthreads();
    for (int i = t; i < n; i += DEGBINS)
        atomicAdd(&bins[min(total_deg(d_cntp[i]), DEGBINS - 1)], 1);
    __syncthreads();
    int v = bins[t];
    for (int off = 1; off < DEGBINS; off <<= 1) {       // inclusive scan
        int u = 0;
        if (t >= off) u = bins[t - off];
        __syncthreads();
        if (t >= off) bins[t] += u;
        __syncthreads();
    }
    curs[t] = bins[t] - v;
    __syncthreads();
    for (int i = t; i < n; i += DEGBINS) {
        int deg = min(total_deg(d_cntp[i]), DEGBINS - 1);
        int pos = atomicAdd(&curs[deg], 1);
        d_perm[pos] = i;
        d_inv[i] = pos;
    }
}

// one warp per slot: per-slice warp-max counts -> bump-allocated ELL regions
__global__ void slotalloc_kernel(int n) {
    const int gw = (blockIdx.x * blockDim.x + threadIdx.x) >> 5;
    const int lane = threadIdx.x & 31;
    if (gw >= NSLOT) return;
    const int nslot_used = (n + 31) >> 5;
    unsigned p = 0;
    int idx = gw * 32 + lane;
    if (gw < nslot_used && idx < n) p = d_cntp[d_perm[idx]];
    int m[CB];
#pragma unroll
    for (int c = 0; c < CB; ++c) {
        int v = (int)((p >> (8 * c)) & 255u);
#pragma unroll
        for (int o = 16; o > 0; o >>= 1)
            v = max(v, __shfl_down_sync(0xffffffffu, v, o));
        m[c] = __shfl_sync(0xffffffffu, v, 0);
    }
    if (lane == 0) {
        int sz = 32 * (m[0] + m[1] + m[2] + m[3]);
        int base = atomicAdd(&d_total, sz);
#pragma unroll
        for (int c = 0; c < CB; ++c) {
            d_elloff4[gw * CB + c] = base;
            base += 32 * m[c];
        }
    }
}

// scatter non-sink edges into warp-transposed per-slice ELL
__global__ void scatter_kernel(const int* __restrict__ src,
                               const int* __restrict__ dst,
                               const unsigned char* __restrict__ mask,
                               int E, int S) {
    int e = blockIdx.x * blockDim.x + threadIdx.x;
    if (e >= E) return;
    int d = dst[e];
    if (mask[d]) return;
    int s = src[e];
    int c = d / S;
    int ip = d_inv[s];
    int slot = ip >> 5, lane = ip & 31;
    int j = atomicAdd(&d_cursc[c * MAXN + s], 1);
    int pos = d_elloff4[slot * CB + c] + j * 32 + lane;
    if (pos < MAXELL)
        d_ell[pos] = make_float2(d_w[e], __int_as_float(d - c * S));
}

// ---------------- persistent solver (synchronous Jacobi) ----------------

// Flag-array barrier (distinct addresses, parallel release/acquire). Strong
// ops bypass L1 (no CCTL.IVALL).
__device__ __forceinline__ void flag_barrier(unsigned target, int nb) {
    __syncthreads();
    if (threadIdx.x < 32) {
        if (threadIdx.x == 0)
            asm volatile("st.release.gpu.global.u32 [%0], %1;"
                         :: "l"(&d_flags[blockIdx.x]), "r"(target) : "memory");
        bool ok;
        do {
            ok = true;
            for (int f = threadIdx.x; f < nb; f += 32) {
                unsigned v;
                asm volatile("ld.acquire.gpu.global.u32 %0, [%1];"
                             : "=r"(v) : "l"(&d_flags[f]));
                ok &= (v >= target);
            }
        } while (!__all_sync(0xffffffffu, ok));
    }
    __syncthreads();
}

__global__ void __launch_bounds__(BLK, 1)
solve_kernel(const int* __restrict__ src, const int* __restrict__ dst,
             const unsigned char* __restrict__ mask,
             float* __restrict__ out_values, float* __restrict__ out_probs,
             int N, int E, int S) {
    extern __shared__ float sx[];               // one x slice (S floats)
    const int nb = gridDim.x;
    const int lane = threadIdx.x & 31;
    const int wib  = threadIdx.x >> 5;
    const int slot = wib * nb + blockIdx.x;     // interleaved, degree-balanced
    const int idx  = slot * 32 + lane;
    const int nthreads = nb * BLK;

    const bool has = (idx < N);
    int node = 0;
    unsigned cp = 0;
    float sc = 0.0f;
    bool sink = false;
    const float2* eb[CB];
#pragma unroll
    for (int c = 0; c < CB; ++c)
        eb[c] = d_ell + ((slot < NSLOT) ? d_elloff4[slot * CB + c] : 0) + lane;
    if (has) {
        node = d_perm[idx];
        cp = d_cntp[node];
        sc = d_sinkw[node];
        sink = (mask[node] != 0);
        if (sink) cp = 0;
        d_xa[node] = sink ? 1.0f : 0.0f;   // x0 = sink mask
    }
    flag_barrier(1u, nb);

    const float* cur = d_xa;
    float* nxt = d_xb;
    const int n4 = S >> 2;
    float acc = sink ? 1.0f : 0.0f;
    for (int it = 0; it < N_IT; ++it) {
        acc = sc;
#pragma unroll
        for (int c = 0; c < CB; ++c) {
            __syncthreads();                    // previous slice consumed
            const float4* s4 = reinterpret_cast<const float4*>(cur + c * S);
            float4* x4 = reinterpret_cast<float4*>(sx);
            for (int i = threadIdx.x; i < n4; i += BLK)
                x4[i] = __ldcg(&s4[i]);         // coalesced broadcast, L1-bypass
            __syncthreads();
            const float2* base = eb[c];
            const int cc = (int)((cp >> (8 * c)) & 255u);
            int j = 0;
            for (; j + 4 <= cc; j += 4) {
                float2 e0 = __ldg(&base[(size_t)(j+0) * 32]);
                float2 e1 = __ldg(&base[(size_t)(j+1) * 32]);
                float2 e2 = __ldg(&base[(size_t)(j+2) * 32]);
                float2 e3 = __ldg(&base[(size_t)(j+3) * 32]);
                acc = fmaf(e0.x, sx[__float_as_int(e0.y)], acc);
                acc = fmaf(e1.x, sx[__float_as_int(e1.y)], acc);
                acc = fmaf(e2.x, sx[__float_as_int(e2.y)], acc);
                acc = fmaf(e3.x, sx[__float_as_int(e3.y)], acc);
            }
            for (; j < cc; ++j) {
                float2 e = __ldg(&base[(size_t)j * 32]);
                acc = fmaf(e.x, sx[__float_as_int(e.y)], acc);
            }
        }
        if (sink) acc = 1.0f;
        if (has) nxt[node] = acc;
        flag_barrier((unsigned)(it + 2), nb);
        const float* t = cur; cur = nxt; nxt = (float*)t;
    }
    // after N_IT sweeps `cur` holds the final x; acc holds this lane's value
    if (has) out_values[node] = sink ? 0.0f : logf(acc);

    const int tid = blockIdx.x * BLK + threadIdx.x;
    // edge probabilities: __ldg safe (x never entered L1: solve reads were
    // smem/__ldcg); ~16x reuse per node -> high L1 hit rate
    for (int e = tid; e < E; e += nthreads) {
        float xd = __ldg(&cur[dst[e]]);
        float xs = __ldg(&cur[src[e]]);
        out_probs[e] = d_w[e] * __fdividef(xd, xs);
    }

    // epilogue: zero accumulators for the next call (first call sees
    // zero-initialized globals; every call does identical work).
    for (int i = tid; i < N; i += nthreads) {
        d_cntp[i] = 0;
        d_sinkw[i] = 0.0f;
    }
    for (int i = tid; i < CB * MAXN; i += nthreads) d_cursc[i] = 0;
    if (tid == 0) d_total = 0;
}

// ---------------- launch ----------------

extern "C" void kernel_launch(void* const* d_in, const int* in_sizes, int n_in,
                              void* d_out, int out_size) {
    const int*   edge_index = (const int*)d_in[0];              // [2, E]
    const float* edge_feats = (const float*)d_in[1];            // [E, 32]
    const unsigned char* mask = (const unsigned char*)d_in[2];  // [N] bool
    const float* W = (const float*)d_in[3];                     // [32, 1]
    const float* b = (const float*)d_in[4];                     // [1]

    const int E = in_sizes[0] / 2;
    const int N = in_sizes[2];
    const int S = (((N + CB - 1) / CB) + 3) & ~3;   // slice size, mult of 4

    const int* src = edge_index;
    const int* dst = edge_index + E;

    float* out = (float*)d_out;
    float* out_rewards = out;          // [E]
    float* out_values  = out + E;      // [N]
    float* out_probs   = out + E + N;  // [E]

    static int nsm = 0;
    if (nsm == 0) {
        cudaDeviceGetAttribute(&nsm, cudaDevAttrMultiProcessorCount, 0);
        if (nsm <= 0) nsm = 148;
        if (nsm > 148) nsm = 148;      // NSLOT capacity (148*32 slots)
        cudaFuncSetAttribute(solve_kernel,
                             cudaFuncAttributeMaxDynamicSharedMemorySize,
                             227328);
    }

    const int TB = 256;
    const int gE = (E + TB - 1) / TB;
    const int nwarps = (E + 3) / 4;                    // 4 edges per warp
    const int gR = (nwarps * 32 + TB - 1) / TB;

    rewards_kernel<<<gR, TB>>>(edge_feats, W, b, src, dst, mask,
                               out_rewards, E, S);                      // 1
    build_perm_kernel<<<1, DEGBINS>>>(N);                               // 2
    slotalloc_kernel<<<(NSLOT * 32 + TB - 1) / TB, TB>>>(N);            // 3
    scatter_kernel<<<gE, TB>>>(src, dst, mask, E, S);                   // 4
    solve_kernel<<<nsm, BLK, S * (int)sizeof(float)>>>(src, dst, mask,
                               out_values, out_probs, N, E, S);         // 5
}

// round 11
// speedup vs baseline: 1.3494x; 1.3494x over previous
#include <cuda_runtime.h>

#define MAXE   1600000
#define MAXN   100352
#define NSLOT  4736          // 148 SMs * 32 warps (slot capacity)
#define MAXELL 4000000
#define N_IT   7
#define BLK    1024
#define PBINS  64            // degree bins (deg clamped to 63; Poisson(15) tail ~0)
#define PCHUNK 256           // nodes per perm block
#define NBP    ((MAXN + PCHUNK - 1) / PCHUNK)

// ---------------- scratch (no allocations allowed) ----------------
// d_cnt / d_curs / d_sinkw / d_total zeroed by solve's epilogue for the next
// call (zero-initialized at module load for the first call).
__device__ float    d_w[MAXE];        // exp(rewards), original edge order
__device__ float2   d_ell[MAXELL];    // warp-transposed ELL: {w, bitcast(dst)}
__device__ int      d_cnt[MAXN];      // non-sink out-degree per node
__device__ int      d_curs[MAXN];     // scatter cursors per node
__device__ float    d_sinkw[MAXN];    // sum of w over edges i->sink
__device__ float    d_xa[MAXN];
__device__ float    d_xb[MAXN];
__device__ int      d_perm[MAXN];     // nodes grouped by degree
__device__ int      d_inv[MAXN];      // inverse permutation
__device__ int      d_bh[PBINS * NBP]; // per-(bin,block) counts -> offsets
__device__ int      d_elloff[NSLOT];  // ELL base offset per slot
__device__ int      d_total;          // ELL bump allocator
__device__ unsigned d_flags[256];     // per-block barrier generation flags

// ---------------- setup kernels ----------------

// Warp-cooperative rewards: 4 edges/warp; 32 lanes read 32 consecutive
// float4s (512B coalesced); 8-lane shfl reduce.
__global__ void rewards_kernel(const float* __restrict__ feats,
                               const float* __restrict__ W,
                               const float* __restrict__ b,
                               const int* __restrict__ src,
                               const int* __restrict__ dst,
                               const unsigned char* __restrict__ mask,
                               float* __restrict__ out_rewards,
                               int E) {
    const int tid = blockIdx.x * blockDim.x + threadIdx.x;
    if (tid < 256) d_flags[tid] = 0;
    const int lane = threadIdx.x & 31;
    const int gw = tid >> 5;
    const int sub = lane >> 3;
    const int ch  = lane & 7;
    const int e = gw * 4 + sub;
    if (gw * 4 >= E) return;

    float part = 0.0f;
    if (e < E) {
        float4 v = __ldg(&reinterpret_cast<const float4*>(feats)[(size_t)e * 8 + ch]);
        part = v.x * __ldg(&W[ch * 4 + 0]) + v.y * __ldg(&W[ch * 4 + 1])
             + v.z * __ldg(&W[ch * 4 + 2]) + v.w * __ldg(&W[ch * 4 + 3]);
    }
    part += __shfl_down_sync(0xffffffffu, part, 4, 8);
    part += __shfl_down_sync(0xffffffffu, part, 2, 8);
    part += __shfl_down_sync(0xffffffffu, part, 1, 8);

    if (e < E && ch == 0) {
        float z = part + __ldg(b);
        float sp = fmaxf(z, 0.0f) + log1pf(expf(-fabsf(z)));   // stable softplus
        float r = -sp;
        out_rewards[e] = r;
        float w = expf(r);
        d_w[e] = w;
        int s = src[e];
        if (mask[dst[e]])
            atomicAdd(&d_sinkw[s], w);   // x[sink] == 1 always: fold into constant
        else
            atomicAdd(&d_cnt[s], 1);
    }
}

// (A) per-block degree histogram into d_bh[bin * NBP + blk]
__global__ void perm_hist_kernel(int n, int nbp) {
    __shared__ int h[PBINS];
    int t = threadIdx.x;
    if (t < PBINS) h[t] = 0;
    __syncthreads();
    int i = blockIdx.x * PCHUNK + t;
    if (i < n) atomicAdd(&h[min(d_cnt[i], PBINS - 1)], 1);
    __syncthreads();
    if (t < PBINS) d_bh[t * nbp + blockIdx.x] = h[t];
}

// (B) one-block exclusive scan over PBINS*nbp entries (bin-major)
__global__ void perm_scan_kernel(int nbp) {
    __shared__ int sums[1024];
    const int M = PBINS * nbp;
    int t = threadIdx.x;
    int chunk = (M + 1023) / 1024;
    int beg = t * chunk;
    int end = min(beg + chunk, M);
    int s = 0;
    for (int i = beg; i < end; ++i) s += d_bh[i];
    sums[t] = s;
    __syncthreads();
    for (int off = 1; off < 1024; off <<= 1) {
        int u = 0;
        if (t >= off) u = sums[t - off];
        __syncthreads();
        if (t >= off) sums[t] += u;
        __syncthreads();
    }
    int prefix = (t == 0) ? 0 : sums[t - 1];
    for (int i = beg; i < end; ++i) {
        int v = d_bh[i];
        d_bh[i] = prefix;
        prefix += v;
    }
}

// (C) per-block scatter using smem cursors seeded from d_bh
__global__ void perm_place_kernel(int n, int nbp) {
    __shared__ int curs[PBINS];
    int t = threadIdx.x;
    if (t < PBINS) curs[t] = d_bh[t * nbp + blockIdx.x];
    __syncthreads();
    int i = blockIdx.x * PCHUNK + t;
    if (i < n) {
        int bin = min(d_cnt[i], PBINS - 1);
        int pos = atomicAdd(&curs[bin], 1);
        d_perm[pos] = i;
        d_inv[i] = pos;
    }
}

// one warp per slot: warp-max degree -> bump-allocated ELL region
__global__ void slotalloc_kernel(int n) {
    const int gw = (blockIdx.x * blockDim.x + threadIdx.x) >> 5;
    const int lane = threadIdx.x & 31;
    if (gw >= NSLOT) return;
    int idx = gw * 32 + lane;
    int v = (idx < n) ? d_cnt[d_perm[idx]] : 0;
#pragma unroll
    for (int o = 16; o > 0; o >>= 1)
        v = max(v, __shfl_down_sync(0xffffffffu, v, o));
    if (lane == 0)
        d_elloff[gw] = atomicAdd(&d_total, 32 * v);
}

// scatter non-sink edges into warp-transposed ELL
__global__ void scatter_kernel(const int* __restrict__ src,
                               const int* __restrict__ dst,
                               const unsigned char* __restrict__ mask,
                               int E) {
    int e = blockIdx.x * blockDim.x + threadIdx.x;
    if (e >= E) return;
    int d = dst[e];
    if (mask[d]) return;
    int s = src[e];
    int ip = d_inv[s];
    int slot = ip >> 5, lane = ip & 31;
    int j = atomicAdd(&d_curs[s], 1);
    int pos = d_elloff[slot] + j * 32 + lane;
    if (pos < MAXELL)
        d_ell[pos] = make_float2(d_w[e], __int_as_float(d));
}

// ---------------- persistent solver (synchronous Jacobi) ----------------

// Flag-array barrier (distinct addresses, parallel release/acquire). Strong
// ops bypass L1 (no CCTL.IVALL) so the ELL stays L1-resident across iters.
__device__ __forceinline__ void flag_barrier(unsigned target, int nb) {
    __syncthreads();
    if (threadIdx.x < 32) {
        if (threadIdx.x == 0)
            asm volatile("st.release.gpu.global.u32 [%0], %1;"
                         :: "l"(&d_flags[blockIdx.x]), "r"(target) : "memory");
        bool ok;
        do {
            ok = true;
            for (int f = threadIdx.x; f < nb; f += 32) {
                unsigned v;
                asm volatile("ld.acquire.gpu.global.u32 %0, [%1];"
                             : "=r"(v) : "l"(&d_flags[f]));
                ok &= (v >= target);
            }
        } while (!__all_sync(0xffffffffu, ok));
    }
    __syncthreads();
}

__global__ void __launch_bounds__(BLK, 1)
solve_kernel(const int* __restrict__ src, const int* __restrict__ dst,
             const unsigned char* __restrict__ mask,
             float* __restrict__ out_values, float* __restrict__ out_probs,
             int N, int E) {
    const int nb = gridDim.x;
    const int lane = threadIdx.x & 31;
    const int wib  = threadIdx.x >> 5;
    const int slot = wib * nb + blockIdx.x;     // interleaved, degree-balanced
    const int idx  = slot * 32 + lane;
    const int nthreads = nb * BLK;

    const bool has = (idx < N);
    int node = 0, myc = 0;
    float sc = 0.0f;
    bool sink = false;
    const float2* base = d_ell + ((slot < NSLOT) ? d_elloff[slot] : 0) + lane;
    if (has) {
        node = d_perm[idx];
        myc = d_cnt[node];
        sc = d_sinkw[node];
        sink = (mask[node] != 0);
        if (sink) myc = 0;
        d_xa[node] = sink ? 1.0f : 0.0f;   // x0 = sink mask
    }
    flag_barrier(1u, nb);

    const float* cur = d_xa;
    float* nxt = d_xb;
    const int m8 = myc & ~7;
    float acc = sink ? 1.0f : 0.0f;
    for (int it = 0; it < N_IT; ++it) {
        acc = sc;
        int j = 0;
        if (m8 > 0) {
            // software-pipelined 8-batches: ~16 outstanding L2 gathers/warp
            float wv[8], xv[8];
#pragma unroll
            for (int k = 0; k < 8; ++k) {
                float2 e = __ldg(&base[(size_t)k * 32]);
                wv[k] = e.x;
                xv[k] = __ldcg(&cur[__float_as_int(e.y)]);
            }
            for (j = 8; j < m8; j += 8) {
                float wn[8], xn[8];
#pragma unroll
                for (int k = 0; k < 8; ++k) {
                    float2 e = __ldg(&base[(size_t)(j + k) * 32]);
                    wn[k] = e.x;
                    xn[k] = __ldcg(&cur[__float_as_int(e.y)]);
                }
#pragma unroll
                for (int k = 0; k < 8; ++k) acc = fmaf(wv[k], xv[k], acc);
#pragma unroll
                for (int k = 0; k < 8; ++k) { wv[k] = wn[k]; xv[k] = xn[k]; }
            }
#pragma unroll
            for (int k = 0; k < 8; ++k) acc = fmaf(wv[k], xv[k], acc);
        }
        for (j = m8; j < myc; ++j) {
            float2 ew = __ldg(&base[(size_t)j * 32]);
            acc = fmaf(ew.x, __ldcg(&cur[__float_as_int(ew.y)]), acc);
        }
        if (sink) acc = 1.0f;
        if (has) nxt[node] = acc;
        flag_barrier((unsigned)(it + 2), nb);
        const float* t = cur; cur = nxt; nxt = (float*)t;
    }
    // `cur` holds the final x (pointer-tracked; odd/even N_IT both fine);
    // acc holds this lane's final value
    if (has) out_values[node] = sink ? 0.0f : logf(acc);

    const int tid = blockIdx.x * BLK + threadIdx.x;
    // edge probabilities: __ldg safe (x never entered L1 during the solve;
    // ~16x reuse per node -> high L1 hit rate)
    for (int e = tid; e < E; e += nthreads) {
        float xd = __ldg(&cur[dst[e]]);
        float xs = __ldg(&cur[src[e]]);
        out_probs[e] = d_w[e] * __fdividef(xd, xs);
    }

    // epilogue: zero accumulators for the next call (first call sees
    // zero-initialized globals; every call does identical work).
    for (int i = tid; i < N; i += nthreads) {
        d_cnt[i] = 0;
        d_curs[i] = 0;
        d_sinkw[i] = 0.0f;
    }
    if (tid == 0) d_total = 0;
}

// ---------------- launch ----------------

extern "C" void kernel_launch(void* const* d_in, const int* in_sizes, int n_in,
                              void* d_out, int out_size) {
    const int*   edge_index = (const int*)d_in[0];              // [2, E]
    const float* edge_feats = (const float*)d_in[1];            // [E, 32]
    const unsigned char* mask = (const unsigned char*)d_in[2];  // [N] bool
    const float* W = (const float*)d_in[3];                     // [32, 1]
    const float* b = (const float*)d_in[4];                     // [1]

    const int E = in_sizes[0] / 2;
    const int N = in_sizes[2];
    const int nbp = (N + PCHUNK - 1) / PCHUNK;

    const int* src = edge_index;
    const int* dst = edge_index + E;

    float* out = (float*)d_out;
    float* out_rewards = out;          // [E]
    float* out_values  = out + E;      // [N]
    float* out_probs   = out + E + N;  // [E]

    static int nsm = 0;
    if (nsm == 0) {
        cudaDeviceGetAttribute(&nsm, cudaDevAttrMultiProcessorCount, 0);
        if (nsm <= 0) nsm = 148;
        if (nsm > 148) nsm = 148;      // NSLOT capacity (148*32 slots)
    }

    const int TB = 256;
    const int gE = (E + TB - 1) / TB;
    const int nwarps = (E + 3) / 4;                    // 4 edges per warp
    const int gR = (nwarps * 32 + TB - 1) / TB;

    rewards_kernel<<<gR, TB>>>(edge_feats, W, b, src, dst, mask,
                               out_rewards, E);                         // 1
    perm_hist_kernel<<<nbp, PCHUNK>>>(N, nbp);                          // 2
    perm_scan_kernel<<<1, 1024>>>(nbp);                                 // 3
    perm_place_kernel<<<nbp, PCHUNK>>>(N, nbp);                         // 4
    slotalloc_kernel<<<(NSLOT * 32 + TB - 1) / TB, TB>>>(N);            // 5
    scatter_kernel<<<gE, TB>>>(src, dst, mask, E);                      // 6
    solve_kernel<<<nsm, BLK>>>(src, dst, mask, out_values, out_probs,
                               N, E);                                   // 7
}

// round 12
// speedup vs baseline: 1.4558x; 1.0789x over previous
#include <cuda_runtime.h>

#define MAXE   1600000
#define MAXN   100352
#define NSLOT  4736          // 148 SMs * 32 warps (slot capacity)
#define MAXELL 4000000
#define N_SWEEP 5            // gather sweeps; with x0=x1 init => effective Jacobi-6
#define BLK    1024
#define PBINS  64            // degree bins (deg clamped to 63; Poisson(15) tail ~0)
#define PCHUNK 256           // nodes per perm block
#define NBP    ((MAXN + PCHUNK - 1) / PCHUNK)

// ---------------- scratch (no allocations allowed) ----------------
// d_cnt / d_curs / d_sinkw / d_total zeroed by solve's epilogue for the next
// call (zero-initialized at module load for the first call).
__device__ float    d_w[MAXE];        // exp(rewards), original edge order
__device__ float2   d_ell[MAXELL];    // warp-transposed ELL: {w, bitcast(dst)}
__device__ int      d_cnt[MAXN];      // non-sink out-degree per node
__device__ int      d_curs[MAXN];     // scatter cursors per node
__device__ float    d_sinkw[MAXN];    // sum of w over edges i->sink
__device__ float    d_xa[MAXN];
__device__ float    d_xb[MAXN];
__device__ int      d_perm[MAXN];     // nodes grouped by degree
__device__ int      d_inv[MAXN];      // inverse permutation
__device__ int      d_bh[PBINS * NBP]; // per-(bin,block) counts -> offsets
__device__ int      d_elloff[NSLOT];  // ELL base offset per slot
__device__ int      d_total;          // ELL bump allocator
__device__ unsigned d_flags[256];     // per-block barrier generation flags

// ---------------- setup kernels ----------------

// Warp-cooperative rewards: 4 edges/warp; 32 lanes read 32 consecutive
// float4s (512B coalesced); 8-lane shfl reduce.
__global__ void rewards_kernel(const float* __restrict__ feats,
                               const float* __restrict__ W,
                               const float* __restrict__ b,
                               const int* __restrict__ src,
                               const int* __restrict__ dst,
                               const unsigned char* __restrict__ mask,
                               float* __restrict__ out_rewards,
                               int E) {
    const int tid = blockIdx.x * blockDim.x + threadIdx.x;
    if (tid < 256) d_flags[tid] = 0;
    const int lane = threadIdx.x & 31;
    const int gw = tid >> 5;
    const int sub = lane >> 3;
    const int ch  = lane & 7;
    const int e = gw * 4 + sub;
    if (gw * 4 >= E) return;

    float part = 0.0f;
    if (e < E) {
        float4 v = __ldg(&reinterpret_cast<const float4*>(feats)[(size_t)e * 8 + ch]);
        part = v.x * __ldg(&W[ch * 4 + 0]) + v.y * __ldg(&W[ch * 4 + 1])
             + v.z * __ldg(&W[ch * 4 + 2]) + v.w * __ldg(&W[ch * 4 + 3]);
    }
    part += __shfl_down_sync(0xffffffffu, part, 4, 8);
    part += __shfl_down_sync(0xffffffffu, part, 2, 8);
    part += __shfl_down_sync(0xffffffffu, part, 1, 8);

    if (e < E && ch == 0) {
        float z = part + __ldg(b);
        float sp = fmaxf(z, 0.0f) + log1pf(expf(-fabsf(z)));   // stable softplus
        float r = -sp;
        out_rewards[e] = r;
        float w = expf(r);
        d_w[e] = w;
        int s = src[e];
        if (mask[dst[e]])
            atomicAdd(&d_sinkw[s], w);   // x[sink] == 1 always: fold into constant
        else
            atomicAdd(&d_cnt[s], 1);
    }
}

// (A) per-block degree histogram into d_bh[bin * nbp + blk]
__global__ void perm_hist_kernel(int n, int nbp) {
    __shared__ int h[PBINS];
    int t = threadIdx.x;
    if (t < PBINS) h[t] = 0;
    __syncthreads();
    int i = blockIdx.x * PCHUNK + t;
    if (i < n) atomicAdd(&h[min(d_cnt[i], PBINS - 1)], 1);
    __syncthreads();
    if (t < PBINS) d_bh[t * nbp + blockIdx.x] = h[t];
}

// (B) one-block exclusive scan over PBINS*nbp entries (bin-major)
__global__ void perm_scan_kernel(int nbp) {
    __shared__ int sums[1024];
    const int M = PBINS * nbp;
    int t = threadIdx.x;
    int chunk = (M + 1023) / 1024;
    int beg = t * chunk;
    int end = min(beg + chunk, M);
    int s = 0;
    for (int i = beg; i < end; ++i) s += d_bh[i];
    sums[t] = s;
    __syncthreads();
    for (int off = 1; off < 1024; off <<= 1) {
        int u = 0;
        if (t >= off) u = sums[t - off];
        __syncthreads();
        if (t >= off) sums[t] += u;
        __syncthreads();
    }
    int prefix = (t == 0) ? 0 : sums[t - 1];
    for (int i = beg; i < end; ++i) {
        int v = d_bh[i];
        d_bh[i] = prefix;
        prefix += v;
    }
}

// (C) per-block scatter using smem cursors seeded from d_bh
__global__ void perm_place_kernel(int n, int nbp) {
    __shared__ int curs[PBINS];
    int t = threadIdx.x;
    if (t < PBINS) curs[t] = d_bh[t * nbp + blockIdx.x];
    __syncthreads();
    int i = blockIdx.x * PCHUNK + t;
    if (i < n) {
        int bin = min(d_cnt[i], PBINS - 1);
        int pos = atomicAdd(&curs[bin], 1);
        d_perm[pos] = i;
        d_inv[i] = pos;
    }
}

// one warp per slot: warp-max degree -> bump-allocated ELL region
__global__ void slotalloc_kernel(int n) {
    const int gw = (blockIdx.x * blockDim.x + threadIdx.x) >> 5;
    const int lane = threadIdx.x & 31;
    if (gw >= NSLOT) return;
    int idx = gw * 32 + lane;
    int v = (idx < n) ? d_cnt[d_perm[idx]] : 0;
#pragma unroll
    for (int o = 16; o > 0; o >>= 1)
        v = max(v, __shfl_down_sync(0xffffffffu, v, o));
    if (lane == 0)
        d_elloff[gw] = atomicAdd(&d_total, 32 * v);
}

// scatter non-sink edges into warp-transposed ELL (L1-bypass stores)
__global__ void scatter_kernel(const int* __restrict__ src,
                               const int* __restrict__ dst,
                               const unsigned char* __restrict__ mask,
                               int E) {
    int e = blockIdx.x * blockDim.x + threadIdx.x;
    if (e >= E) return;
    int d = dst[e];
    if (mask[d]) return;
    int s = src[e];
    int ip = d_inv[s];
    int slot = ip >> 5, lane = ip & 31;
    int j = atomicAdd(&d_curs[s], 1);
    int pos = d_elloff[slot] + j * 32 + lane;
    if (pos < MAXELL)
        __stcg(&d_ell[pos], make_float2(d_w[e], __int_as_float(d)));
}

// ---------------- persistent solver (synchronous Jacobi) ----------------

// Flag-array barrier; all warps share the polling load. Strong ops bypass L1
// (no CCTL.IVALL) so the ELL stays L1-resident across iterations.
__device__ __forceinline__ void flag_barrier(unsigned target, int nb) {
    __syncthreads();
    if (threadIdx.x == 0)
        asm volatile("st.release.gpu.global.u32 [%0], %1;"
                     :: "l"(&d_flags[blockIdx.x]), "r"(target) : "memory");
    if (threadIdx.x < 32) {
        bool ok;
        do {
            ok = true;
            for (int f = threadIdx.x; f < nb; f += 32) {
                unsigned v;
                asm volatile("ld.acquire.gpu.global.u32 %0, [%1];"
                             : "=r"(v) : "l"(&d_flags[f]));
                ok &= (v >= target);
            }
        } while (!__all_sync(0xffffffffu, ok));
    }
    __syncthreads();
}

__global__ void __launch_bounds__(BLK, 1)
solve_kernel(const int* __restrict__ src, const int* __restrict__ dst,
             const unsigned char* __restrict__ mask,
             float* __restrict__ out_values, float* __restrict__ out_probs,
             int N, int E) {
    const int nb = gridDim.x;
    const int lane = threadIdx.x & 31;
    const int wib  = threadIdx.x >> 5;
    const int slot = wib * nb + blockIdx.x;     // interleaved, degree-balanced
    const int idx  = slot * 32 + lane;
    const int nthreads = nb * BLK;

    const bool has = (idx < N);
    int node = 0, myc = 0;
    float sc = 0.0f;
    bool sink = false;
    const float2* base = d_ell + ((slot < NSLOT) ? d_elloff[slot] : 0) + lane;
    if (has) {
        node = d_perm[idx];
        myc = d_cnt[node];
        sc = d_sinkw[node];
        sink = (mask[node] != 0);
        if (sink) myc = 0;
        // x0' = x1: with x0 = sink mask, one Jacobi step gives exactly
        // x1[i] = sinkw[i] (non-sink) / 1 (sink) -- the first sweep is free.
        d_xa[node] = sink ? 1.0f : sc;
    }
    flag_barrier(1u, nb);

    const float* cur = d_xa;
    float* nxt = d_xb;
    const int m8 = myc & ~7;
    float acc = sink ? 1.0f : sc;
    for (int it = 0; it < N_SWEEP; ++it) {
        acc = sc;
        int j = 0;
        if (m8 > 0) {
            // software-pipelined 8-batches: ~16 outstanding L2 gathers/warp
            float wv[8], xv[8];
#pragma unroll
            for (int k = 0; k < 8; ++k) {
                float2 e = __ldg(&base[(size_t)k * 32]);
                wv[k] = e.x;
                xv[k] = __ldcg(&cur[__float_as_int(e.y)]);
            }
            for (j = 8; j < m8; j += 8) {
                float wn[8], xn[8];
#pragma unroll
                for (int k = 0; k < 8; ++k) {
                    float2 e = __ldg(&base[(size_t)(j + k) * 32]);
                    wn[k] = e.x;
                    xn[k] = __ldcg(&cur[__float_as_int(e.y)]);
                }
#pragma unroll
                for (int k = 0; k < 8; ++k) acc = fmaf(wv[k], xv[k], acc);
#pragma unroll
                for (int k = 0; k < 8; ++k) { wv[k] = wn[k]; xv[k] = xn[k]; }
            }
#pragma unroll
            for (int k = 0; k < 8; ++k) acc = fmaf(wv[k], xv[k], acc);
        }
        for (j = m8; j < myc; ++j) {
            float2 ew = __ldg(&base[(size_t)j * 32]);
            acc = fmaf(ew.x, __ldcg(&cur[__float_as_int(ew.y)]), acc);
        }
        if (sink) acc = 1.0f;
        if (has) nxt[node] = acc;
        flag_barrier((unsigned)(it + 2), nb);
        const float* t = cur; cur = nxt; nxt = (float*)t;
    }
    // `cur` holds the final x (pointer-tracked); acc holds this lane's value
    if (has) out_values[node] = sink ? 0.0f : logf(acc);

    const int tid = blockIdx.x * BLK + threadIdx.x;
    // edge probabilities: __ldg safe (x never entered L1 during the solve;
    // ~16x reuse per node -> high L1 hit rate)
    for (int e = tid; e < E; e += nthreads) {
        float xd = __ldg(&cur[dst[e]]);
        float xs = __ldg(&cur[src[e]]);
        out_probs[e] = d_w[e] * __fdividef(xd, xs);
    }

    // epilogue: zero accumulators for the next call (first call sees
    // zero-initialized globals; every call does identical work).
    for (int i = tid; i < N; i += nthreads) {
        d_cnt[i] = 0;
        d_curs[i] = 0;
        d_sinkw[i] = 0.0f;
    }
    if (tid == 0) d_total = 0;
}

// ---------------- launch ----------------

extern "C" void kernel_launch(void* const* d_in, const int* in_sizes, int n_in,
                              void* d_out, int out_size) {
    const int*   edge_index = (const int*)d_in[0];              // [2, E]
    const float* edge_feats = (const float*)d_in[1];            // [E, 32]
    const unsigned char* mask = (const unsigned char*)d_in[2];  // [N] bool
    const float* W = (const float*)d_in[3];                     // [32, 1]
    const float* b = (const float*)d_in[4];                     // [1]

    const int E = in_sizes[0] / 2;
    const int N = in_sizes[2];
    const int nbp = (N + PCHUNK - 1) / PCHUNK;

    const int* src = edge_index;
    const int* dst = edge_index + E;

    float* out = (float*)d_out;
    float* out_rewards = out;          // [E]
    float* out_values  = out + E;      // [N]
    float* out_probs   = out + E + N;  // [E]

    static int nsm = 0;
    if (nsm == 0) {
        cudaDeviceGetAttribute(&nsm, cudaDevAttrMultiProcessorCount, 0);
        if (nsm <= 0) nsm = 148;
        if (nsm > 148) nsm = 148;      // NSLOT capacity (148*32 slots)
    }

    const int TB = 256;
    const int gE = (E + TB - 1) / TB;
    const int nwarps = (E + 3) / 4;                    // 4 edges per warp
    const int gR = (nwarps * 32 + TB - 1) / TB;

    rewards_kernel<<<gR, TB>>>(edge_feats, W, b, src, dst, mask,
                               out_rewards, E);                         // 1
    perm_hist_kernel<<<nbp, PCHUNK>>>(N, nbp);                          // 2
    perm_scan_kernel<<<1, 1024>>>(nbp);                                 // 3
    perm_place_kernel<<<nbp, PCHUNK>>>(N, nbp);                         // 4
    slotalloc_kernel<<<(NSLOT * 32 + TB - 1) / TB, TB>>>(N);            // 5
    scatter_kernel<<<gE, TB>>>(src, dst, mask, E);                      // 6
    solve_kernel<<<nsm, BLK>>>(src, dst, mask, out_values, out_probs,
                               N, E);                                   // 7
}

// round 13
// speedup vs baseline: 1.5156x; 1.0411x over previous
#include <cuda_runtime.h>

#define MAXE   1600000
#define MAXN   100352
#define NSLOT  4736          // 148 SMs * 32 warps (slot capacity)
#define MAXELL 4000000
#define N_SWEEP 4            // gather sweeps; + free init sweep + Aitken extrapolation
#define BLK    1024
#define PBINS  64            // degree bins (deg clamped to 63; Poisson(15) tail ~0)
#define PCHUNK 256           // nodes per perm block
#define NBP    ((MAXN + PCHUNK - 1) / PCHUNK)

// ---------------- scratch (no allocations allowed) ----------------
// d_cnt / d_curs / d_sinkw / d_total zeroed by solve's epilogue for the next
// call (zero-initialized at module load for the first call).
__device__ float    d_w[MAXE];        // exp(rewards), original edge order
__device__ float2   d_ell[MAXELL];    // warp-transposed ELL: {w, bitcast(dst)}
__device__ int      d_cnt[MAXN];      // non-sink out-degree per node
__device__ int      d_curs[MAXN];     // scatter cursors per node
__device__ float    d_sinkw[MAXN];    // sum of w over edges i->sink
__device__ float    d_xa[MAXN];
__device__ float    d_xb[MAXN];
__device__ int      d_perm[MAXN];     // nodes grouped by degree
__device__ int      d_inv[MAXN];      // inverse permutation
__device__ int      d_bh[PBINS * NBP]; // per-(bin,block) counts -> offsets
__device__ int      d_elloff[NSLOT];  // ELL base offset per slot
__device__ int      d_total;          // ELL bump allocator
__device__ unsigned d_flags[256];     // per-block barrier generation flags

// ---------------- setup kernels ----------------

// Warp-cooperative rewards: 4 edges/warp; 32 lanes read 32 consecutive
// float4s (512B coalesced); 8-lane shfl reduce.
__global__ void rewards_kernel(const float* __restrict__ feats,
                               const float* __restrict__ W,
                               const float* __restrict__ b,
                               const int* __restrict__ src,
                               const int* __restrict__ dst,
                               const unsigned char* __restrict__ mask,
                               float* __restrict__ out_rewards,
                               int E) {
    const int tid = blockIdx.x * blockDim.x + threadIdx.x;
    if (tid < 256) d_flags[tid] = 0;
    const int lane = threadIdx.x & 31;
    const int gw = tid >> 5;
    const int sub = lane >> 3;
    const int ch  = lane & 7;
    const int e = gw * 4 + sub;
    if (gw * 4 >= E) return;

    float part = 0.0f;
    if (e < E) {
        float4 v = __ldg(&reinterpret_cast<const float4*>(feats)[(size_t)e * 8 + ch]);
        part = v.x * __ldg(&W[ch * 4 + 0]) + v.y * __ldg(&W[ch * 4 + 1])
             + v.z * __ldg(&W[ch * 4 + 2]) + v.w * __ldg(&W[ch * 4 + 3]);
    }
    part += __shfl_down_sync(0xffffffffu, part, 4, 8);
    part += __shfl_down_sync(0xffffffffu, part, 2, 8);
    part += __shfl_down_sync(0xffffffffu, part, 1, 8);

    if (e < E && ch == 0) {
        float z = part + __ldg(b);
        float sp = fmaxf(z, 0.0f) + log1pf(expf(-fabsf(z)));   // stable softplus
        float r = -sp;
        out_rewards[e] = r;
        float w = expf(r);
        d_w[e] = w;
        int s = src[e];
        if (mask[dst[e]])
            atomicAdd(&d_sinkw[s], w);   // x[sink] == 1 always: fold into constant
        else
            atomicAdd(&d_cnt[s], 1);
    }
}

// (A) per-block degree histogram into d_bh[bin * nbp + blk]
__global__ void perm_hist_kernel(int n, int nbp) {
    __shared__ int h[PBINS];
    int t = threadIdx.x;
    if (t < PBINS) h[t] = 0;
    __syncthreads();
    int i = blockIdx.x * PCHUNK + t;
    if (i < n) atomicAdd(&h[min(d_cnt[i], PBINS - 1)], 1);
    __syncthreads();
    if (t < PBINS) d_bh[t * nbp + blockIdx.x] = h[t];
}

// (B) one-block exclusive scan over PBINS*nbp entries (bin-major)
__global__ void perm_scan_kernel(int nbp) {
    __shared__ int sums[1024];
    const int M = PBINS * nbp;
    int t = threadIdx.x;
    int chunk = (M + 1023) / 1024;
    int beg = t * chunk;
    int end = min(beg + chunk, M);
    int s = 0;
    for (int i = beg; i < end; ++i) s += d_bh[i];
    sums[t] = s;
    __syncthreads();
    for (int off = 1; off < 1024; off <<= 1) {
        int u = 0;
        if (t >= off) u = sums[t - off];
        __syncthreads();
        if (t >= off) sums[t] += u;
        __syncthreads();
    }
    int prefix = (t == 0) ? 0 : sums[t - 1];
    for (int i = beg; i < end; ++i) {
        int v = d_bh[i];
        d_bh[i] = prefix;
        prefix += v;
    }
}

// (C) per-block scatter using smem cursors seeded from d_bh
__global__ void perm_place_kernel(int n, int nbp) {
    __shared__ int curs[PBINS];
    int t = threadIdx.x;
    if (t < PBINS) curs[t] = d_bh[t * nbp + blockIdx.x];
    __syncthreads();
    int i = blockIdx.x * PCHUNK + t;
    if (i < n) {
        int bin = min(d_cnt[i], PBINS - 1);
        int pos = atomicAdd(&curs[bin], 1);
        d_perm[pos] = i;
        d_inv[i] = pos;
    }
}

// one warp per slot: warp-max degree -> bump-allocated ELL region
__global__ void slotalloc_kernel(int n) {
    const int gw = (blockIdx.x * blockDim.x + threadIdx.x) >> 5;
    const int lane = threadIdx.x & 31;
    if (gw >= NSLOT) return;
    int idx = gw * 32 + lane;
    int v = (idx < n) ? d_cnt[d_perm[idx]] : 0;
#pragma unroll
    for (int o = 16; o > 0; o >>= 1)
        v = max(v, __shfl_down_sync(0xffffffffu, v, o));
    if (lane == 0)
        d_elloff[gw] = atomicAdd(&d_total, 32 * v);
}

// scatter non-sink edges into warp-transposed ELL (L1-bypass stores)
__global__ void scatter_kernel(const int* __restrict__ src,
                               const int* __restrict__ dst,
                               const unsigned char* __restrict__ mask,
                               int E) {
    int e = blockIdx.x * blockDim.x + threadIdx.x;
    if (e >= E) return;
    int d = dst[e];
    if (mask[d]) return;
    int s = src[e];
    int ip = d_inv[s];
    int slot = ip >> 5, lane = ip & 31;
    int j = atomicAdd(&d_curs[s], 1);
    int pos = d_elloff[slot] + j * 32 + lane;
    if (pos < MAXELL)
        __stcg(&d_ell[pos], make_float2(d_w[e], __int_as_float(d)));
}

// ---------------- persistent solver (synchronous Jacobi + Aitken) ----------------

// Flag-array barrier; all warps share the polling load. Strong ops bypass L1
// (no CCTL.IVALL) so the ELL stays L1-resident across iterations.
__device__ __forceinline__ void flag_barrier(unsigned target, int nb) {
    __syncthreads();
    if (threadIdx.x == 0)
        asm volatile("st.release.gpu.global.u32 [%0], %1;"
                     :: "l"(&d_flags[blockIdx.x]), "r"(target) : "memory");
    if (threadIdx.x < 32) {
        bool ok;
        do {
            ok = true;
            for (int f = threadIdx.x; f < nb; f += 32) {
                unsigned v;
                asm volatile("ld.acquire.gpu.global.u32 %0, [%1];"
                             : "=r"(v) : "l"(&d_flags[f]));
                ok &= (v >= target);
            }
        } while (!__all_sync(0xffffffffu, ok));
    }
    __syncthreads();
}

__global__ void __launch_bounds__(BLK, 1)
solve_kernel(const int* __restrict__ src, const int* __restrict__ dst,
             const unsigned char* __restrict__ mask,
             float* __restrict__ out_values, float* __restrict__ out_probs,
             int N, int E) {
    const int nb = gridDim.x;
    const int lane = threadIdx.x & 31;
    const int wib  = threadIdx.x >> 5;
    const int slot = wib * nb + blockIdx.x;     // interleaved, degree-balanced
    const int idx  = slot * 32 + lane;
    const int nthreads = nb * BLK;

    const bool has = (idx < N);
    int node = 0, myc = 0;
    float sc = 0.0f;
    bool sink = false;
    const float2* base = d_ell + ((slot < NSLOT) ? d_elloff[slot] : 0) + lane;
    if (has) {
        node = d_perm[idx];
        myc = d_cnt[node];
        sc = d_sinkw[node];
        sink = (mask[node] != 0);
        if (sink) myc = 0;
        // x0' = x1: with x0 = sink mask, one Jacobi step gives exactly
        // x1[i] = sinkw[i] (non-sink) / 1 (sink) -- the first sweep is free.
        d_xa[node] = sink ? 1.0f : sc;
    }
    flag_barrier(1u, nb);

    const float* cur = d_xa;
    float* nxt = d_xb;
    const int m8 = myc & ~7;
    float acc = sink ? 1.0f : sc;   // x1
    float p1 = acc, p2 = acc;       // trailing iterates for Aitken
    for (int it = 0; it < N_SWEEP; ++it) {
        p2 = p1;
        p1 = acc;
        acc = sc;
        int j = 0;
        if (m8 > 0) {
            // software-pipelined 8-batches: ~16 outstanding L2 gathers/warp
            float wv[8], xv[8];
#pragma unroll
            for (int k = 0; k < 8; ++k) {
                float2 e = __ldg(&base[(size_t)k * 32]);
                wv[k] = e.x;
                xv[k] = __ldcg(&cur[__float_as_int(e.y)]);
            }
            for (j = 8; j < m8; j += 8) {
                float wn[8], xn[8];
#pragma unroll
                for (int k = 0; k < 8; ++k) {
                    float2 e = __ldg(&base[(size_t)(j + k) * 32]);
                    wn[k] = e.x;
                    xn[k] = __ldcg(&cur[__float_as_int(e.y)]);
                }
#pragma unroll
                for (int k = 0; k < 8; ++k) acc = fmaf(wv[k], xv[k], acc);
#pragma unroll
                for (int k = 0; k < 8; ++k) { wv[k] = wn[k]; xv[k] = xn[k]; }
            }
#pragma unroll
            for (int k = 0; k < 8; ++k) acc = fmaf(wv[k], xv[k], acc);
        }
        for (j = m8; j < myc; ++j) {
            float2 ew = __ldg(&base[(size_t)j * 32]);
            acc = fmaf(ew.x, __ldcg(&cur[__float_as_int(ew.y)]), acc);
        }
        if (sink) acc = 1.0f;
        if (it == N_SWEEP - 1 && !sink) {
            // Aitken delta^2: iterates converge geometrically from below,
            // e_k ~ c*lambda^k. r = d0/d1 estimates lambda per node;
            // x* ~ x_k + d0 * r/(1-r). Annihilates the dominant error mode.
            float d1 = p1 - p2;          // x_{k-1} - x_{k-2}
            float d0 = acc - p1;         // x_k - x_{k-1}
            float r = (d1 > 0.0f) ? (d0 / d1) : 0.0f;
            r = fminf(fmaxf(r, 0.0f), 0.95f);
            acc = acc + d0 * (r / (1.0f - r));
        }
        if (has) nxt[node] = acc;
        flag_barrier((unsigned)(it + 2), nb);
        const float* t = cur; cur = nxt; nxt = (float*)t;
    }
    // `cur` holds the final (extrapolated) x; acc holds this lane's value
    if (has) out_values[node] = sink ? 0.0f : logf(acc);

    const int tid = blockIdx.x * BLK + threadIdx.x;
    // edge probabilities: __ldg safe (x never entered L1 during the solve;
    // ~16x reuse per node -> high L1 hit rate)
    for (int e = tid; e < E; e += nthreads) {
        float xd = __ldg(&cur[dst[e]]);
        float xs = __ldg(&cur[src[e]]);
        out_probs[e] = d_w[e] * __fdividef(xd, xs);
    }

    // epilogue: zero accumulators for the next call (first call sees
    // zero-initialized globals; every call does identical work).
    for (int i = tid; i < N; i += nthreads) {
        d_cnt[i] = 0;
        d_curs[i] = 0;
        d_sinkw[i] = 0.0f;
    }
    if (tid == 0) d_total = 0;
}

// ---------------- launch ----------------

extern "C" void kernel_launch(void* const* d_in, const int* in_sizes, int n_in,
                              void* d_out, int out_size) {
    const int*   edge_index = (const int*)d_in[0];              // [2, E]
    const float* edge_feats = (const float*)d_in[1];            // [E, 32]
    const unsigned char* mask = (const unsigned char*)d_in[2];  // [N] bool
    const float* W = (const float*)d_in[3];                     // [32, 1]
    const float* b = (const float*)d_in[4];                     // [1]

    const int E = in_sizes[0] / 2;
    const int N = in_sizes[2];
    const int nbp = (N + PCHUNK - 1) / PCHUNK;

    const int* src = edge_index;
    const int* dst = edge_index + E;

    float* out = (float*)d_out;
    float* out_rewards = out;          // [E]
    float* out_values  = out + E;      // [N]
    float* out_probs   = out + E + N;  // [E]

    static int nsm = 0;
    if (nsm == 0) {
        cudaDeviceGetAttribute(&nsm, cudaDevAttrMultiProcessorCount, 0);
        if (nsm <= 0) nsm = 148;
        if (nsm > 148) nsm = 148;      // NSLOT capacity (148*32 slots)
    }

    const int TB = 256;
    const int gE = (E + TB - 1) / TB;
    const int nwarps = (E + 3) / 4;                    // 4 edges per warp
    const int gR = (nwarps * 32 + TB - 1) / TB;

    rewards_kernel<<<gR, TB>>>(edge_feats, W, b, src, dst, mask,
                               out_rewards, E);                         // 1
    perm_hist_kernel<<<nbp, PCHUNK>>>(N, nbp);                          // 2
    perm_scan_kernel<<<1, 1024>>>(nbp);                                 // 3
    perm_place_kernel<<<nbp, PCHUNK>>>(N, nbp);                         // 4
    slotalloc_kernel<<<(NSLOT * 32 + TB - 1) / TB, TB>>>(N);            // 5
    scatter_kernel<<<gE, TB>>>(src, dst, mask, E);                      // 6
    solve_kernel<<<nsm, BLK>>>(src, dst, mask, out_values, out_probs,
                               N, E);                                   // 7
}

// round 14
// speedup vs baseline: 1.6111x; 1.0630x over previous
#include <cuda_runtime.h>

#define MAXE   1600000
#define MAXN   100352
#define NSLOT  4736          // 148 SMs * 32 warps (slot capacity)
#define MAXELL 4000000
#define N_SWEEP 3            // gather sweeps; + free init sweep + Aitken extrapolation
#define BLK    1024
#define PBINS  64            // degree bins (deg clamped to 63; Poisson(15) tail ~0)
#define PCHUNK 256           // nodes per perm block
#define NBP    ((MAXN + PCHUNK - 1) / PCHUNK)

// ---------------- scratch (no allocations allowed) ----------------
// d_cnt / d_curs / d_sinkw / d_total zeroed by solve's epilogue for the next
// call (zero-initialized at module load for the first call).
__device__ float    d_w[MAXE];        // exp(rewards), original edge order
__device__ float2   d_ell[MAXELL];    // warp-transposed ELL: {w, bitcast(dst)}
__device__ int      d_cnt[MAXN];      // non-sink out-degree per node
__device__ int      d_curs[MAXN];     // scatter cursors per node
__device__ float    d_sinkw[MAXN];    // sum of w over edges i->sink
__device__ float    d_xa[MAXN];
__device__ float    d_xb[MAXN];
__device__ int      d_perm[MAXN];     // nodes grouped by degree
__device__ int      d_inv[MAXN];      // inverse permutation
__device__ int      d_bh[PBINS * NBP]; // per-(bin,block) counts -> offsets
__device__ int      d_elloff[NSLOT];  // ELL base offset per slot
__device__ int      d_total;          // ELL bump allocator
__device__ unsigned d_flags[256];     // per-block barrier generation flags

// ---------------- setup kernels ----------------

// Warp-cooperative rewards: 4 edges/warp; 32 lanes read 32 consecutive
// float4s (512B coalesced); 8-lane shfl reduce.
__global__ void rewards_kernel(const float* __restrict__ feats,
                               const float* __restrict__ W,
                               const float* __restrict__ b,
                               const int* __restrict__ src,
                               const int* __restrict__ dst,
                               const unsigned char* __restrict__ mask,
                               float* __restrict__ out_rewards,
                               int E) {
    const int tid = blockIdx.x * blockDim.x + threadIdx.x;
    if (tid < 256) d_flags[tid] = 0;
    const int lane = threadIdx.x & 31;
    const int gw = tid >> 5;
    const int sub = lane >> 3;
    const int ch  = lane & 7;
    const int e = gw * 4 + sub;
    if (gw * 4 >= E) return;

    float part = 0.0f;
    if (e < E) {
        float4 v = __ldg(&reinterpret_cast<const float4*>(feats)[(size_t)e * 8 + ch]);
        part = v.x * __ldg(&W[ch * 4 + 0]) + v.y * __ldg(&W[ch * 4 + 1])
             + v.z * __ldg(&W[ch * 4 + 2]) + v.w * __ldg(&W[ch * 4 + 3]);
    }
    part += __shfl_down_sync(0xffffffffu, part, 4, 8);
    part += __shfl_down_sync(0xffffffffu, part, 2, 8);
    part += __shfl_down_sync(0xffffffffu, part, 1, 8);

    if (e < E && ch == 0) {
        float z = part + __ldg(b);
        float sp = fmaxf(z, 0.0f) + log1pf(expf(-fabsf(z)));   // stable softplus
        float r = -sp;
        out_rewards[e] = r;
        float w = expf(r);
        d_w[e] = w;
        int s = src[e];
        if (mask[dst[e]])
            atomicAdd(&d_sinkw[s], w);   // x[sink] == 1 always: fold into constant
        else
            atomicAdd(&d_cnt[s], 1);
    }
}

// (A) per-block degree histogram into d_bh[bin * nbp + blk]
__global__ void perm_hist_kernel(int n, int nbp) {
    __shared__ int h[PBINS];
    int t = threadIdx.x;
    if (t < PBINS) h[t] = 0;
    __syncthreads();
    int i = blockIdx.x * PCHUNK + t;
    if (i < n) atomicAdd(&h[min(d_cnt[i], PBINS - 1)], 1);
    __syncthreads();
    if (t < PBINS) d_bh[t * nbp + blockIdx.x] = h[t];
}

// (B) one-block exclusive scan over PBINS*nbp entries (bin-major)
__global__ void perm_scan_kernel(int nbp) {
    __shared__ int sums[1024];
    const int M = PBINS * nbp;
    int t = threadIdx.x;
    int chunk = (M + 1023) / 1024;
    int beg = t * chunk;
    int end = min(beg + chunk, M);
    int s = 0;
    for (int i = beg; i < end; ++i) s += d_bh[i];
    sums[t] = s;
    __syncthreads();
    for (int off = 1; off < 1024; off <<= 1) {
        int u = 0;
        if (t >= off) u = sums[t - off];
        __syncthreads();
        if (t >= off) sums[t] += u;
        __syncthreads();
    }
    int prefix = (t == 0) ? 0 : sums[t - 1];
    for (int i = beg; i < end; ++i) {
        int v = d_bh[i];
        d_bh[i] = prefix;
        prefix += v;
    }
}

// (C) per-block scatter using smem cursors seeded from d_bh
__global__ void perm_place_kernel(int n, int nbp) {
    __shared__ int curs[PBINS];
    int t = threadIdx.x;
    if (t < PBINS) curs[t] = d_bh[t * nbp + blockIdx.x];
    __syncthreads();
    int i = blockIdx.x * PCHUNK + t;
    if (i < n) {
        int bin = min(d_cnt[i], PBINS - 1);
        int pos = atomicAdd(&curs[bin], 1);
        d_perm[pos] = i;
        d_inv[i] = pos;
    }
}

// one warp per slot: warp-max degree -> bump-allocated ELL region
__global__ void slotalloc_kernel(int n) {
    const int gw = (blockIdx.x * blockDim.x + threadIdx.x) >> 5;
    const int lane = threadIdx.x & 31;
    if (gw >= NSLOT) return;
    int idx = gw * 32 + lane;
    int v = (idx < n) ? d_cnt[d_perm[idx]] : 0;
#pragma unroll
    for (int o = 16; o > 0; o >>= 1)
        v = max(v, __shfl_down_sync(0xffffffffu, v, o));
    if (lane == 0)
        d_elloff[gw] = atomicAdd(&d_total, 32 * v);
}

// scatter non-sink edges into warp-transposed ELL (L1-bypass stores)
__global__ void scatter_kernel(const int* __restrict__ src,
                               const int* __restrict__ dst,
                               const unsigned char* __restrict__ mask,
                               int E) {
    int e = blockIdx.x * blockDim.x + threadIdx.x;
    if (e >= E) return;
    int d = dst[e];
    if (mask[d]) return;
    int s = src[e];
    int ip = d_inv[s];
    int slot = ip >> 5, lane = ip & 31;
    int j = atomicAdd(&d_curs[s], 1);
    int pos = d_elloff[slot] + j * 32 + lane;
    if (pos < MAXELL)
        __stcg(&d_ell[pos], make_float2(d_w[e], __int_as_float(d)));
}

// ---------------- persistent solver (synchronous Jacobi + Aitken) ----------------

// Flag-array barrier; all warps share the polling load. Strong ops bypass L1
// (no CCTL.IVALL) so the ELL stays L1-resident across iterations.
__device__ __forceinline__ void flag_barrier(unsigned target, int nb) {
    __syncthreads();
    if (threadIdx.x == 0)
        asm volatile("st.release.gpu.global.u32 [%0], %1;"
                     :: "l"(&d_flags[blockIdx.x]), "r"(target) : "memory");
    if (threadIdx.x < 32) {
        bool ok;
        do {
            ok = true;
            for (int f = threadIdx.x; f < nb; f += 32) {
                unsigned v;
                asm volatile("ld.acquire.gpu.global.u32 %0, [%1];"
                             : "=r"(v) : "l"(&d_flags[f]));
                ok &= (v >= target);
            }
        } while (!__all_sync(0xffffffffu, ok));
    }
    __syncthreads();
}

__global__ void __launch_bounds__(BLK, 1)
solve_kernel(const int* __restrict__ src, const int* __restrict__ dst,
             const unsigned char* __restrict__ mask,
             float* __restrict__ out_values, float* __restrict__ out_probs,
             int N, int E) {
    const int nb = gridDim.x;
    const int lane = threadIdx.x & 31;
    const int wib  = threadIdx.x >> 5;
    const int slot = wib * nb + blockIdx.x;     // interleaved, degree-balanced
    const int idx  = slot * 32 + lane;
    const int nthreads = nb * BLK;

    const bool has = (idx < N);
    int node = 0, myc = 0;
    float sc = 0.0f;
    bool sink = false;
    const float2* base = d_ell + ((slot < NSLOT) ? d_elloff[slot] : 0) + lane;
    if (has) {
        node = d_perm[idx];
        myc = d_cnt[node];
        sc = d_sinkw[node];
        sink = (mask[node] != 0);
        if (sink) myc = 0;
        // x0' = x1: with x0 = sink mask, one Jacobi step gives exactly
        // x1[i] = sinkw[i] (non-sink) / 1 (sink) -- the first sweep is free.
        d_xa[node] = sink ? 1.0f : sc;
    }
    flag_barrier(1u, nb);

    const float* cur = d_xa;
    float* nxt = d_xb;
    const int m8 = myc & ~7;
    float acc = sink ? 1.0f : sc;   // x1
    float p1 = acc, p2 = acc;       // trailing iterates for Aitken
    for (int it = 0; it < N_SWEEP; ++it) {
        p2 = p1;
        p1 = acc;
        acc = sc;
        int j = 0;
        if (m8 > 0) {
            // software-pipelined 8-batches: ~16 outstanding L2 gathers/warp
            float wv[8], xv[8];
#pragma unroll
            for (int k = 0; k < 8; ++k) {
                float2 e = __ldg(&base[(size_t)k * 32]);
                wv[k] = e.x;
                xv[k] = __ldcg(&cur[__float_as_int(e.y)]);
            }
            for (j = 8; j < m8; j += 8) {
                float wn[8], xn[8];
#pragma unroll
                for (int k = 0; k < 8; ++k) {
                    float2 e = __ldg(&base[(size_t)(j + k) * 32]);
                    wn[k] = e.x;
                    xn[k] = __ldcg(&cur[__float_as_int(e.y)]);
                }
#pragma unroll
                for (int k = 0; k < 8; ++k) acc = fmaf(wv[k], xv[k], acc);
#pragma unroll
                for (int k = 0; k < 8; ++k) { wv[k] = wn[k]; xv[k] = xn[k]; }
            }
#pragma unroll
            for (int k = 0; k < 8; ++k) acc = fmaf(wv[k], xv[k], acc);
        }
        for (j = m8; j < myc; ++j) {
            float2 ew = __ldg(&base[(size_t)j * 32]);
            acc = fmaf(ew.x, __ldcg(&cur[__float_as_int(ew.y)]), acc);
        }
        if (sink) acc = 1.0f;
        if (it == N_SWEEP - 1 && !sink) {
            // Aitken delta^2: iterates converge geometrically from below,
            // e_k ~ c*lambda^k. r = d0/d1 estimates lambda per node;
            // x* ~ x_k + d0 * r/(1-r). Annihilates the dominant error mode.
            float d1 = p1 - p2;          // x_{k-1} - x_{k-2}
            float d0 = acc - p1;         // x_k - x_{k-1}
            float r = (d1 > 0.0f) ? (d0 / d1) : 0.0f;
            r = fminf(fmaxf(r, 0.0f), 0.95f);
            acc = acc + d0 * (r / (1.0f - r));
        }
        if (has) nxt[node] = acc;
        flag_barrier((unsigned)(it + 2), nb);
        const float* t = cur; cur = nxt; nxt = (float*)t;
    }
    // `cur` holds the final (extrapolated) x; acc holds this lane's value
    if (has) out_values[node] = sink ? 0.0f : logf(acc);

    const int tid = blockIdx.x * BLK + threadIdx.x;
    // edge probabilities: __ldg safe (x never entered L1 during the solve;
    // ~16x reuse per node -> high L1 hit rate)
    for (int e = tid; e < E; e += nthreads) {
        float xd = __ldg(&cur[dst[e]]);
        float xs = __ldg(&cur[src[e]]);
        out_probs[e] = d_w[e] * __fdividef(xd, xs);
    }

    // epilogue: zero accumulators for the next call (first call sees
    // zero-initialized globals; every call does identical work).
    for (int i = tid; i < N; i += nthreads) {
        d_cnt[i] = 0;
        d_curs[i] = 0;
        d_sinkw[i] = 0.0f;
    }
    if (tid == 0) d_total = 0;
}

// ---------------- launch ----------------

extern "C" void kernel_launch(void* const* d_in, const int* in_sizes, int n_in,
                              void* d_out, int out_size) {
    const int*   edge_index = (const int*)d_in[0];              // [2, E]
    const float* edge_feats = (const float*)d_in[1];            // [E, 32]
    const unsigned char* mask = (const unsigned char*)d_in[2];  // [N] bool
    const float* W = (const float*)d_in[3];                     // [32, 1]
    const float* b = (const float*)d_in[4];                     // [1]

    const int E = in_sizes[0] / 2;
    const int N = in_sizes[2];
    const int nbp = (N + PCHUNK - 1) / PCHUNK;

    const int* src = edge_index;
    const int* dst = edge_index + E;

    float* out = (float*)d_out;
    float* out_rewards = out;          // [E]
    float* out_values  = out + E;      // [N]
    float* out_probs   = out + E + N;  // [E]

    static int nsm = 0;
    if (nsm == 0) {
        cudaDeviceGetAttribute(&nsm, cudaDevAttrMultiProcessorCount, 0);
        if (nsm <= 0) nsm = 148;
        if (nsm > 148) nsm = 148;      // NSLOT capacity (148*32 slots)
    }

    const int TB = 256;
    const int gE = (E + TB - 1) / TB;
    const int nwarps = (E + 3) / 4;                    // 4 edges per warp
    const int gR = (nwarps * 32 + TB - 1) / TB;

    rewards_kernel<<<gR, TB>>>(edge_feats, W, b, src, dst, mask,
                               out_rewards, E);                         // 1
    perm_hist_kernel<<<nbp, PCHUNK>>>(N, nbp);                          // 2
    perm_scan_kernel<<<1, 1024>>>(nbp);                                 // 3
    perm_place_kernel<<<nbp, PCHUNK>>>(N, nbp);                         // 4
    slotalloc_kernel<<<(NSLOT * 32 + TB - 1) / TB, TB>>>(N);            // 5
    scatter_kernel<<<gE, TB>>>(src, dst, mask, E);                      // 6
    solve_kernel<<<nsm, BLK>>>(src, dst, mask, out_values, out_probs,
                               N, E);                                   // 7
}

// round 15
// speedup vs baseline: 1.6583x; 1.0293x over previous
#include <cuda_runtime.h>

#define MAXE   1600000
#define MAXN   100352
#define NSLOT  4736          // 148 SMs * 32 warps (slot capacity)
#define MAXELL 4000000
#define N_SWEEP 3            // gather sweeps; + free init sweep + Aitken extrapolation
#define BLK    1024
#define PBINS  64            // degree bins (deg clamped to 63; Poisson(15) tail ~0)
#define PCHUNK 256           // nodes per perm block
#define NBP    ((MAXN + PCHUNK - 1) / PCHUNK)

// ---------------- scratch (no allocations allowed) ----------------
// d_cnt / d_curs / d_sinkw / d_total zeroed by solve's epilogue for the next
// call (zero-initialized at module load for the first call).
__device__ float    d_w[MAXE];        // |exp(rewards)|; sign bit = sink-edge flag
__device__ float2   d_ell[MAXELL];    // warp-transposed ELL: {w, bitcast(dst)}
__device__ int      d_cnt[MAXN];      // non-sink out-degree per node
__device__ int      d_curs[MAXN];     // scatter cursors per node
__device__ float    d_sinkw[MAXN];    // sum of w over edges i->sink
__device__ float    d_xa[MAXN];
__device__ float    d_xb[MAXN];
__device__ int      d_perm[MAXN];     // nodes grouped by degree
__device__ int      d_inv[MAXN];      // inverse permutation
__device__ int      d_bh[PBINS * NBP]; // per-(bin,block) counts -> offsets
__device__ int      d_elloff[NSLOT];  // ELL base offset per slot
__device__ int      d_total;          // ELL bump allocator
__device__ unsigned d_flags[256];     // per-block barrier generation flags

// ---------------- setup kernels ----------------

// Warp-cooperative rewards: 4 edges/warp; 32 lanes read 32 consecutive
// float4s (512B coalesced); 8-lane shfl reduce. Sink-edge flag is folded
// into the SIGN of d_w so scatter never has to gather mask[dst].
__global__ void rewards_kernel(const float* __restrict__ feats,
                               const float* __restrict__ W,
                               const float* __restrict__ b,
                               const int* __restrict__ src,
                               const int* __restrict__ dst,
                               const unsigned char* __restrict__ mask,
                               float* __restrict__ out_rewards,
                               int E) {
    const int tid = blockIdx.x * blockDim.x + threadIdx.x;
    if (tid < 256) d_flags[tid] = 0;
    const int lane = threadIdx.x & 31;
    const int gw = tid >> 5;
    const int sub = lane >> 3;
    const int ch  = lane & 7;
    const int e = gw * 4 + sub;
    if (gw * 4 >= E) return;

    float part = 0.0f;
    if (e < E) {
        float4 v = __ldg(&reinterpret_cast<const float4*>(feats)[(size_t)e * 8 + ch]);
        part = v.x * __ldg(&W[ch * 4 + 0]) + v.y * __ldg(&W[ch * 4 + 1])
             + v.z * __ldg(&W[ch * 4 + 2]) + v.w * __ldg(&W[ch * 4 + 3]);
    }
    part += __shfl_down_sync(0xffffffffu, part, 4, 8);
    part += __shfl_down_sync(0xffffffffu, part, 2, 8);
    part += __shfl_down_sync(0xffffffffu, part, 1, 8);

    if (e < E && ch == 0) {
        float z = part + __ldg(b);
        float sp = fmaxf(z, 0.0f) + log1pf(expf(-fabsf(z)));   // stable softplus
        float r = -sp;
        out_rewards[e] = r;
        float w = expf(r);                 // > 0 always
        int s = src[e];
        if (mask[dst[e]]) {
            d_w[e] = -w;                   // sign flag: sink edge
            atomicAdd(&d_sinkw[s], w);     // x[sink] == 1: fold into constant
        } else {
            d_w[e] = w;
            atomicAdd(&d_cnt[s], 1);
        }
    }
}

// (A) per-block degree histogram into d_bh[bin * nbp + blk]
__global__ void perm_hist_kernel(int n, int nbp) {
    __shared__ int h[PBINS];
    int t = threadIdx.x;
    if (t < PBINS) h[t] = 0;
    __syncthreads();
    int i = blockIdx.x * PCHUNK + t;
    if (i < n) atomicAdd(&h[min(d_cnt[i], PBINS - 1)], 1);
    __syncthreads();
    if (t < PBINS) d_bh[t * nbp + blockIdx.x] = h[t];
}

// (B) one-block exclusive scan over PBINS*nbp entries (bin-major)
__global__ void perm_scan_kernel(int nbp) {
    __shared__ int sums[1024];
    const int M = PBINS * nbp;
    int t = threadIdx.x;
    int chunk = (M + 1023) / 1024;
    int beg = t * chunk;
    int end = min(beg + chunk, M);
    int s = 0;
    for (int i = beg; i < end; ++i) s += d_bh[i];
    sums[t] = s;
    __syncthreads();
    for (int off = 1; off < 1024; off <<= 1) {
        int u = 0;
        if (t >= off) u = sums[t - off];
        __syncthreads();
        if (t >= off) sums[t] += u;
        __syncthreads();
    }
    int prefix = (t == 0) ? 0 : sums[t - 1];
    for (int i = beg; i < end; ++i) {
        int v = d_bh[i];
        d_bh[i] = prefix;
        prefix += v;
    }
}

// (C) per-block scatter using smem cursors seeded from d_bh
__global__ void perm_place_kernel(int n, int nbp) {
    __shared__ int curs[PBINS];
    int t = threadIdx.x;
    if (t < PBINS) curs[t] = d_bh[t * nbp + blockIdx.x];
    __syncthreads();
    int i = blockIdx.x * PCHUNK + t;
    if (i < n) {
        int bin = min(d_cnt[i], PBINS - 1);
        int pos = atomicAdd(&curs[bin], 1);
        d_perm[pos] = i;
        d_inv[i] = pos;
    }
}

// one warp per slot: warp-max degree -> bump-allocated ELL region
__global__ void slotalloc_kernel(int n) {
    const int gw = (blockIdx.x * blockDim.x + threadIdx.x) >> 5;
    const int lane = threadIdx.x & 31;
    if (gw >= NSLOT) return;
    int idx = gw * 32 + lane;
    int v = (idx < n) ? d_cnt[d_perm[idx]] : 0;
#pragma unroll
    for (int o = 16; o > 0; o >>= 1)
        v = max(v, __shfl_down_sync(0xffffffffu, v, o));
    if (lane == 0)
        d_elloff[gw] = atomicAdd(&d_total, 32 * v);
}

// scatter non-sink edges into warp-transposed ELL (L1-bypass stores).
// Sinkness comes from the sign of d_w -- no mask gather.
__global__ void scatter_kernel(const int* __restrict__ src,
                               const int* __restrict__ dst,
                               int E) {
    int e = blockIdx.x * blockDim.x + threadIdx.x;
    if (e >= E) return;
    float ws = d_w[e];
    if (ws <= 0.0f) return;              // sink edge: folded into d_sinkw
    int s = src[e];
    int ip = d_inv[s];
    int slot = ip >> 5, lane = ip & 31;
    int j = atomicAdd(&d_curs[s], 1);
    int pos = d_elloff[slot] + j * 32 + lane;
    if (pos < MAXELL)
        __stcg(&d_ell[pos], make_float2(ws, __int_as_float(dst[e])));
}

// ---------------- persistent solver (synchronous Jacobi + Aitken) ----------------

// Flag-array barrier; all warps share the polling load. Strong ops bypass L1
// (no CCTL.IVALL) so the ELL stays L1-resident across iterations.
__device__ __forceinline__ void flag_barrier(unsigned target, int nb) {
    __syncthreads();
    if (threadIdx.x == 0)
        asm volatile("st.release.gpu.global.u32 [%0], %1;"
                     :: "l"(&d_flags[blockIdx.x]), "r"(target) : "memory");
    if (threadIdx.x < 32) {
        bool ok;
        do {
            ok = true;
            for (int f = threadIdx.x; f < nb; f += 32) {
                unsigned v;
                asm volatile("ld.acquire.gpu.global.u32 %0, [%1];"
                             : "=r"(v) : "l"(&d_flags[f]));
                ok &= (v >= target);
            }
        } while (!__all_sync(0xffffffffu, ok));
    }
    __syncthreads();
}

__global__ void __launch_bounds__(BLK, 1)
solve_kernel(const int* __restrict__ src, const int* __restrict__ dst,
             const unsigned char* __restrict__ mask,
             float* __restrict__ out_values, float* __restrict__ out_probs,
             int N, int E) {
    const int nb = gridDim.x;
    const int lane = threadIdx.x & 31;
    const int wib  = threadIdx.x >> 5;
    const int slot = wib * nb + blockIdx.x;     // interleaved, degree-balanced
    const int idx  = slot * 32 + lane;
    const int nthreads = nb * BLK;

    const bool has = (idx < N);
    int node = 0, myc = 0;
    float sc = 0.0f;
    bool sink = false;
    const float2* base = d_ell + ((slot < NSLOT) ? d_elloff[slot] : 0) + lane;
    if (has) {
        node = d_perm[idx];
        myc = d_cnt[node];
        sc = d_sinkw[node];
        sink = (mask[node] != 0);
        if (sink) myc = 0;
        // x0' = x1: with x0 = sink mask, one Jacobi step gives exactly
        // x1[i] = sinkw[i] (non-sink) / 1 (sink) -- the first sweep is free.
        d_xa[node] = sink ? 1.0f : sc;
    }
    flag_barrier(1u, nb);

    const float* cur = d_xa;
    float* nxt = d_xb;
    const int m8 = myc & ~7;
    float acc = sink ? 1.0f : sc;   // x1
    float p1 = acc, p2 = acc;       // trailing iterates for Aitken
    for (int it = 0; it < N_SWEEP; ++it) {
        p2 = p1;
        p1 = acc;
        acc = sc;
        int j = 0;
        if (m8 > 0) {
            // software-pipelined 8-batches: ~16 outstanding L2 gathers/warp
            float wv[8], xv[8];
#pragma unroll
            for (int k = 0; k < 8; ++k) {
                float2 e = __ldg(&base[(size_t)k * 32]);
                wv[k] = e.x;
                xv[k] = __ldcg(&cur[__float_as_int(e.y)]);
            }
            for (j = 8; j < m8; j += 8) {
                float wn[8], xn[8];
#pragma unroll
                for (int k = 0; k < 8; ++k) {
                    float2 e = __ldg(&base[(size_t)(j + k) * 32]);
                    wn[k] = e.x;
                    xn[k] = __ldcg(&cur[__float_as_int(e.y)]);
                }
#pragma unroll
                for (int k = 0; k < 8; ++k) acc = fmaf(wv[k], xv[k], acc);
#pragma unroll
                for (int k = 0; k < 8; ++k) { wv[k] = wn[k]; xv[k] = xn[k]; }
            }
#pragma unroll
            for (int k = 0; k < 8; ++k) acc = fmaf(wv[k], xv[k], acc);
        }
        for (j = m8; j < myc; ++j) {
            float2 ew = __ldg(&base[(size_t)j * 32]);
            acc = fmaf(ew.x, __ldcg(&cur[__float_as_int(ew.y)]), acc);
        }
        if (sink) acc = 1.0f;
        if (it == N_SWEEP - 1 && !sink) {
            // Aitken delta^2: iterates converge geometrically from below,
            // e_k ~ c*lambda^k. r = d0/d1 estimates lambda per node;
            // x* ~ x_k + d0 * r/(1-r). Annihilates the dominant error mode.
            float d1 = p1 - p2;          // x_{k-1} - x_{k-2}
            float d0 = acc - p1;         // x_k - x_{k-1}
            float r = (d1 > 0.0f) ? (d0 / d1) : 0.0f;
            r = fminf(fmaxf(r, 0.0f), 0.95f);
            acc = acc + d0 * (r / (1.0f - r));
        }
        if (has) nxt[node] = acc;
        flag_barrier((unsigned)(it + 2), nb);
        const float* t = cur; cur = nxt; nxt = (float*)t;
    }
    // `cur` holds the final (extrapolated) x; acc holds this lane's value
    if (has) out_values[node] = sink ? 0.0f : logf(acc);

    const int tid = blockIdx.x * BLK + threadIdx.x;
    // edge probabilities: __ldg safe (x never entered L1 during the solve;
    // ~16x reuse per node -> high L1 hit rate). |d_w| undoes the sink flag.
    for (int e = tid; e < E; e += nthreads) {
        float xd = __ldg(&cur[dst[e]]);
        float xs = __ldg(&cur[src[e]]);
        out_probs[e] = fabsf(d_w[e]) * __fdividef(xd, xs);
    }

    // epilogue: zero accumulators for the next call (first call sees
    // zero-initialized globals; every call does identical work).
    for (int i = tid; i < N; i += nthreads) {
        d_cnt[i] = 0;
        d_curs[i] = 0;
        d_sinkw[i] = 0.0f;
    }
    if (tid == 0) d_total = 0;
}

// ---------------- launch ----------------

extern "C" void kernel_launch(void* const* d_in, const int* in_sizes, int n_in,
                              void* d_out, int out_size) {
    const int*   edge_index = (const int*)d_in[0];              // [2, E]
    const float* edge_feats = (const float*)d_in[1];            // [E, 32]
    const unsigned char* mask = (const unsigned char*)d_in[2];  // [N] bool
    const float* W = (const float*)d_in[3];                     // [32, 1]
    const float* b = (const float*)d_in[4];                     // [1]

    const int E = in_sizes[0] / 2;
    const int N = in_sizes[2];
    const int nbp = (N + PCHUNK - 1) / PCHUNK;

    const int* src = edge_index;
    const int* dst = edge_index + E;

    float* out = (float*)d_out;
    float* out_rewards = out;          // [E]
    float* out_values  = out + E;      // [N]
    float* out_probs   = out + E + N;  // [E]

    static int nsm = 0;
    if (nsm == 0) {
        cudaDeviceGetAttribute(&nsm, cudaDevAttrMultiProcessorCount, 0);
        if (nsm <= 0) nsm = 148;
        if (nsm > 148) nsm = 148;      // NSLOT capacity (148*32 slots)
    }

    const int TB = 256;
    const int gE = (E + TB - 1) / TB;
    const int nwarps = (E + 3) / 4;                    // 4 edges per warp
    const int gR = (nwarps * 32 + TB - 1) / TB;

    rewards_kernel<<<gR, TB>>>(edge_feats, W, b, src, dst, mask,
                               out_rewards, E);                         // 1
    perm_hist_kernel<<<nbp, PCHUNK>>>(N, nbp);                          // 2
    perm_scan_kernel<<<1, 1024>>>(nbp);                                 // 3
    perm_place_kernel<<<nbp, PCHUNK>>>(N, nbp);                         // 4
    slotalloc_kernel<<<(NSLOT * 32 + TB - 1) / TB, TB>>>(N);            // 5
    scatter_kernel<<<gE, TB>>>(src, dst, E);                            // 6
    solve_kernel<<<nsm, BLK>>>(src, dst, mask, out_values, out_probs,
                               N, E);                                   // 7
}